// round 14
// baseline (speedup 1.0000x reference)
#include <cuda_runtime.h>
#include <cuda_bf16.h>
#include <mma.h>
#include <cstdint>

using namespace nvcuda;

// ================= static scratch (no allocs allowed) =================
#define MAXN 10240
#define MAXW 320   // ceil(MAXN/32)
#define CSR_STRIDE 96

__device__ float   g_P[MAXN * 256];
__device__ float   g_Q[MAXN * 256];
__device__ float   g_nbr[MAXN * 256];
__device__ float   g_f2[MAXN * 256];
__device__ float   g_S1[MAXN * 256];
__device__ float   g_T1[MAXN * 256];
__device__ unsigned g_AB[MAXN * MAXW];
__device__ unsigned g_RB[MAXN * MAXW];
__device__ int     g_degcnt[MAXN];
__device__ int     g_csrp[MAXN * CSR_STRIDE];
__device__ float   g_cnt2[MAXN];
__device__ int     g_sync;     // grid barrier counter for fused_prep (reset by hop1)
// pre-split bf16 weights, [k][n] row-major per job: 655360 bf16 each
__device__ __nv_bfloat16 g_Bh[655360];
__device__ __nv_bfloat16 g_Bl[655360];
// bf16 copy of node_tokens (feat2 GEMM B-matrix); written by tokenizer GEMM epilogue
__device__ __nv_bfloat16 g_NTb[MAXN * 256];

// ================= small ptx helpers =================
__device__ __forceinline__ uint32_t smem_u32(const void* p) {
    uint32_t a;
    asm("{ .reg .u64 t; cvta.to.shared.u64 t, %1; cvt.u32.u64 %0, t; }" : "=r"(a) : "l"(p));
    return a;
}
#define CP_COMMIT() asm volatile("cp.async.commit_group;" ::: "memory")
#define CP_WAIT0()  asm volatile("cp.async.wait_group 0;" ::: "memory")

// ================= fused prep: zero + weight split + grid barrier + CSR/bitset build =================
struct PrepJob { const float* W; int K; int boff; };

__global__ __launch_bounds__(256)
void fused_prep(const int* __restrict__ row, const int* __restrict__ col, int E,
                PrepJob p0, PrepJob p1, PrepJob p2, PrepJob p3,
                PrepJob p4, PrepJob p5, PrepJob p6, int n, int words) {
    int tid = threadIdx.x;
    size_t gid = (size_t)blockIdx.x * blockDim.x + tid;
    size_t stride = (size_t)gridDim.x * blockDim.x;   // 148*256 = 37888

    // ---- phase 1: zero the accumulating scratch ----
    size_t ztot = (size_t)n * words;
    for (size_t i = gid; i < ztot; i += stride) {
        g_AB[i] = 0u;
        if (i < (size_t)n) g_degcnt[i] = 0;
    }

    // ---- grid barrier (all 148 CTAs resident by construction) ----
    __threadfence();
    __syncthreads();
    if (tid == 0) {
        atomicAdd(&g_sync, 1);
        while (*(volatile int*)&g_sync < (int)gridDim.x) {}
    }
    __syncthreads();

    // ---- phase 2a: per-edge degree + padded CSR + adjacency bitset ----
    for (size_t e = gid; e < (size_t)E; e += stride) {
        int r = row[e], c = col[e];
        int slot = atomicAdd(&g_degcnt[r], 1);
        if (slot < CSR_STRIDE) g_csrp[r * CSR_STRIDE + slot] = c;
        atomicOr(&g_AB[(size_t)r * words + (c >> 5)], 1u << (c & 31));
    }

    // ---- phase 2b: split weights to bf16 hi/lo (independent of edges) ----
    PrepJob jobs[7] = {p0, p1, p2, p3, p4, p5, p6};
    const int total = 655360;
    for (size_t e = gid; e < (size_t)total; e += stride) {
        int rem = (int)e, j = 0;
        while (rem >= 256 * jobs[j].K) { rem -= 256 * jobs[j].K; j++; }
        int nn = rem & 255;
        int k  = rem >> 8;
        float x = jobs[j].W[(size_t)k * 256 + nn];
        __nv_bfloat16 h = __float2bfloat16(x);
        __nv_bfloat16 l = __float2bfloat16(x - __bfloat162float(h));
        int dst = jobs[j].boff + k * 256 + nn;
        g_Bh[dst] = h;
        g_Bl[dst] = l;
    }
}

// ================= 1-hop: nbr_mean + reach bitset + cnt2 (also resets g_sync) =================
__global__ void hop1_kernel(const float* __restrict__ NT, int n, int words) {
    if (blockIdx.x == 0 && threadIdx.x == 0) g_sync = 0;   // replay-safe barrier reset
    int i = blockIdx.x;
    int t = threadIdx.x;
    int t2 = 256 + t;
    int deg = g_degcnt[i];
    int cnt = deg < CSR_STRIDE ? deg : CSR_STRIDE;
    const int* csr = &g_csrp[i * CSR_STRIDE];
    unsigned w0 = 0u, w1 = 0u;
    float acc = 0.f;
    for (int p = 0; p < cnt; p++) {
        int j = csr[p];
        const unsigned* abr = &g_AB[(size_t)j * words];
        if (t < words)  w0 |= abr[t];
        if (t2 < words) w1 |= abr[t2];
        acc += NT[(size_t)j * 256 + t];
    }
    int wi = i >> 5;
    unsigned sb = 1u << (i & 31);
    if (wi == t)  w0 &= ~sb;
    if (wi == t2) w1 &= ~sb;
    if (t < words)  g_RB[(size_t)i * words + t]  = w0;
    if (t2 < words) g_RB[(size_t)i * words + t2] = w1;

    float inv = deg > 0 ? 1.f / (float)deg : 0.f;
    g_nbr[(size_t)i * 256 + t] = acc * inv;

    __shared__ int red[256];
    red[t] = __popc(w0) + __popc(w1);
    __syncthreads();
    for (int off = 128; off > 0; off >>= 1) {
        if (t < off) red[t] += red[t + off];
        __syncthreads();
    }
    if (t == 0) g_cnt2[i] = (float)red[0];
}

// ================= edge tokens: 32B/thread, streaming stores =================
__global__ void edge_tok_kernel(const int* __restrict__ row, const int* __restrict__ col,
                                float* __restrict__ out2, int E) {
    long long idx = (long long)blockIdx.x * blockDim.x + threadIdx.x;
    long long total = (long long)E * 32;
    if (idx >= total) return;
    int e = (int)(idx >> 5);
    int u = (int)(idx & 31) << 1;
    int r = row[e], c = col[e];
    const float4* P4 = reinterpret_cast<const float4*>(g_P);
    const float4* Q4 = reinterpret_cast<const float4*>(g_Q);
    float4 a0 = P4[(size_t)r * 64 + u];
    float4 a1 = P4[(size_t)r * 64 + u + 1];
    float4 b0 = Q4[(size_t)c * 64 + u];
    float4 b1 = Q4[(size_t)c * 64 + u + 1];
    float4 o0, o1;
    o0.x = a0.x + b0.x; o0.y = a0.y + b0.y; o0.z = a0.z + b0.z; o0.w = a0.w + b0.w;
    o1.x = a1.x + b1.x; o1.y = a1.y + b1.y; o1.z = a1.z + b1.z; o1.w = a1.w + b1.w;
    float4* dst = reinterpret_cast<float4*>(out2) + ((size_t)e * 64 + u);
    __stcs(dst, o0);
    __stcs(dst + 1, o1);
}

// ================= feat2 v7: dense mask GEMM, K=128 stages (PROFILED SLOT) =================
#define FG_LDA 136
#define FG_LDB 136
#define FGS_A 0
#define FGS_B 17408
#define FGS_TOTAL 52224

__global__ __launch_bounds__(256, 4)
void feat2_gemm(int n, int words, int nstages) {
    extern __shared__ __align__(16) char fsm[];
    uint32_t sbase = smem_u32(fsm);
    __nv_bfloat16* Ab = (__nv_bfloat16*)(fsm + FGS_A);
    __nv_bfloat16* Bb = (__nv_bfloat16*)(fsm + FGS_B);
    float* stage = (float*)(fsm + FGS_A);

    int tid  = threadIdx.x;
    int warp = tid >> 5;
    int lane = tid & 31;
    int wm = warp >> 1;
    int wn = warp & 1;
    int row0 = blockIdx.y * 64;
    int col0 = blockIdx.x * 128;

    wmma::fragment<wmma::accumulator, 16, 16, 16, float> acc[4];
#pragma unroll
    for (int j = 0; j < 4; j++) wmma::fill_fragment(acc[j], 0.f);

    int ar = tid >> 2;
    int aq = tid & 3;
    int anode = row0 + ar;

    for (int st = 0; st < nstages; st++) {
        {
            int k0 = st * 128;
#pragma unroll
            for (int u = 0; u < 8; u++) {
                int v = tid + u * 256;
                int k = v >> 4;
                int n16 = (v & 15) << 3;
                uint32_t dst = sbase + FGS_B + (k * FG_LDB + n16) * 2;
                const char* src;
                int sz;
                if (k0 + k < n) {
                    src = (const char*)&g_NTb[(size_t)(k0 + k) * 256 + col0 + n16];
                    sz = 16;
                } else {
                    src = (const char*)&g_NTb[0];
                    sz = 0;
                }
                asm volatile("cp.async.cg.shared.global [%0], [%1], 16, %2;"
                             :: "r"(dst), "l"(src), "r"(sz));
            }
            CP_COMMIT();
        }
#pragma unroll
        for (int gsel = 0; gsel < 2; gsel++) {
            int g = aq + gsel * 4;
            unsigned wordv = 0u;
            int widx = st * 4 + (g >> 1);
            if (anode < n && widx < words) wordv = g_RB[(size_t)anode * words + widx];
            unsigned bits = (wordv >> ((g & 1) * 16)) & 0xFFFFu;
            uint32_t pk[8];
#pragma unroll
            for (int i = 0; i < 8; i++) {
                uint32_t lo = (bits >> (2 * i)) & 1u;
                uint32_t hi = (bits >> (2 * i + 1)) & 1u;
                pk[i] = (lo ? 0x3F80u : 0u) | (hi ? 0x3F800000u : 0u);
            }
            uint32_t* dst = reinterpret_cast<uint32_t*>(&Ab[ar * FG_LDA + g * 16]);
            *reinterpret_cast<uint4*>(dst)     = make_uint4(pk[0], pk[1], pk[2], pk[3]);
            *reinterpret_cast<uint4*>(dst + 4) = make_uint4(pk[4], pk[5], pk[6], pk[7]);
        }
        CP_WAIT0();
        __syncthreads();

#pragma unroll
        for (int ks = 0; ks < 8; ks++) {
            wmma::fragment<wmma::matrix_a, 16, 16, 16, __nv_bfloat16, wmma::row_major> af;
            wmma::load_matrix_sync(af, &Ab[(wm * 16) * FG_LDA + ks * 16], FG_LDA);
#pragma unroll
            for (int j = 0; j < 4; j++) {
                wmma::fragment<wmma::matrix_b, 16, 16, 16, __nv_bfloat16, wmma::row_major> bf;
                wmma::load_matrix_sync(bf, &Bb[(ks * 16) * FG_LDB + wn * 64 + j * 16], FG_LDB);
                wmma::mma_sync(acc[j], af, bf, acc[j]);
            }
        }
        __syncthreads();
    }

    int er = lane >> 1;
    int ec = (lane & 1) << 3;
    float* st = &stage[warp * 320];
#pragma unroll
    for (int j = 0; j < 4; j++) {
        wmma::store_matrix_sync(st, acc[j], 20, wmma::mem_row_major);
        __syncwarp();
        int grow = row0 + wm * 16 + er;
        int gcol = col0 + wn * 64 + j * 16 + ec;
        if (grow < n) {
            float c = g_cnt2[grow];
            float inv = c > 0.f ? 1.f / c : 0.f;
            float o[8];
#pragma unroll
            for (int q = 0; q < 8; q++) o[q] = st[er * 20 + ec + q] * inv;
            *reinterpret_cast<float4*>(&g_f2[(size_t)grow * 256 + gcol]) =
                *reinterpret_cast<float4*>(&o[0]);
            *reinterpret_cast<float4*>(&g_f2[(size_t)grow * 256 + gcol + 4]) =
                *reinterpret_cast<float4*>(&o[4]);
        }
        __syncwarp();
    }
}

// ================= GEMM: wmma bf16 hi/lo 3-pass, 128x128 tile =================
struct GJob {
    const float* A0; const float* A1; const float* A2;
    const float* bias; float* C;
    __nv_bfloat16* bfcopy;
    int boff; int nblk; int relu;
};

#define W8_AH 0
#define W8_AL 18432
#define W8_BH 36864
#define W8_BL 54272
#define W8_ST 71680
#define W8_TOTAL 81920

#define LDA 72
#define LDB 136

__global__ __launch_bounds__(256, 2)
void gemm_wmma(GJob j0, GJob j1, GJob j2, int M) {
    extern __shared__ __align__(32) char smem[];
    __nv_bfloat16* Ah = (__nv_bfloat16*)(smem + W8_AH);
    __nv_bfloat16* Al = (__nv_bfloat16*)(smem + W8_AL);
    __nv_bfloat16* Bh = (__nv_bfloat16*)(smem + W8_BH);
    __nv_bfloat16* Bl = (__nv_bfloat16*)(smem + W8_BL);
    float* stage = (float*)(smem + W8_ST);

    GJob jb = (blockIdx.z == 0) ? j0 : ((blockIdx.z == 1) ? j1 : j2);
    int tid  = threadIdx.x;
    int warp = tid >> 5;
    int lane = tid & 31;
    int wm = warp >> 1;
    int wn = warp & 1;
    int row0 = blockIdx.y * 128;
    int col0 = blockIdx.x * 128;

    wmma::fragment<wmma::accumulator, 16, 16, 16, float> acc[2][4];
#pragma unroll
    for (int i = 0; i < 2; i++)
#pragma unroll
        for (int j = 0; j < 4; j++) wmma::fill_fragment(acc[i][j], 0.f);

    int a_r = tid >> 1;
    int a_c = (tid & 1) << 5;
    int gar = row0 + a_r;

    int nchunks = jb.nblk * 4;
    for (int ch = 0; ch < nchunks; ch++) {
        int kt = ch * 64;
        const float* Ap = (kt < 256) ? jb.A0 : ((kt < 512) ? jb.A1 : jb.A2);
        int ko = kt & 255;

#pragma unroll
        for (int u = 0; u < 8; u++) {
            int c = a_c + u * 4;
            float4 x = make_float4(0.f, 0.f, 0.f, 0.f);
            if (gar < M) x = *reinterpret_cast<const float4*>(&Ap[(size_t)gar * 256 + ko + c]);
            __nv_bfloat16 h0 = __float2bfloat16(x.x);
            __nv_bfloat16 h1 = __float2bfloat16(x.y);
            __nv_bfloat16 h2 = __float2bfloat16(x.z);
            __nv_bfloat16 h3 = __float2bfloat16(x.w);
            __nv_bfloat16 l0 = __float2bfloat16(x.x - __bfloat162float(h0));
            __nv_bfloat16 l1 = __float2bfloat16(x.y - __bfloat162float(h1));
            __nv_bfloat16 l2 = __float2bfloat16(x.z - __bfloat162float(h2));
            __nv_bfloat16 l3 = __float2bfloat16(x.w - __bfloat162float(h3));
            uint32_t hA = (uint32_t)__bfloat16_as_ushort(h0) | ((uint32_t)__bfloat16_as_ushort(h1) << 16);
            uint32_t hB = (uint32_t)__bfloat16_as_ushort(h2) | ((uint32_t)__bfloat16_as_ushort(h3) << 16);
            uint32_t lA = (uint32_t)__bfloat16_as_ushort(l0) | ((uint32_t)__bfloat16_as_ushort(l1) << 16);
            uint32_t lB = (uint32_t)__bfloat16_as_ushort(l2) | ((uint32_t)__bfloat16_as_ushort(l3) << 16);
            *reinterpret_cast<uint2*>(&Ah[a_r * LDA + c]) = make_uint2(hA, hB);
            *reinterpret_cast<uint2*>(&Al[a_r * LDA + c]) = make_uint2(lA, lB);
        }
        {
            int boff = jb.boff + kt * 256 + col0;
#pragma unroll
            for (int u = 0; u < 4; u++) {
                int v = tid + u * 256;
                int k = v >> 4;
                int n8 = (v & 15) << 3;
                *reinterpret_cast<uint4*>(&Bh[k * LDB + n8]) =
                    *reinterpret_cast<const uint4*>(&g_Bh[boff + k * 256 + n8]);
                *reinterpret_cast<uint4*>(&Bl[k * LDB + n8]) =
                    *reinterpret_cast<const uint4*>(&g_Bl[boff + k * 256 + n8]);
            }
        }
        __syncthreads();

#pragma unroll
        for (int ks = 0; ks < 4; ks++) {
            wmma::fragment<wmma::matrix_a, 16, 16, 16, __nv_bfloat16, wmma::row_major> ah[2], al[2];
#pragma unroll
            for (int i = 0; i < 2; i++) {
                wmma::load_matrix_sync(ah[i], &Ah[(wm * 32 + i * 16) * LDA + ks * 16], LDA);
                wmma::load_matrix_sync(al[i], &Al[(wm * 32 + i * 16) * LDA + ks * 16], LDA);
            }
#pragma unroll
            for (int j = 0; j < 4; j++) {
                wmma::fragment<wmma::matrix_b, 16, 16, 16, __nv_bfloat16, wmma::row_major> bh, bl;
                wmma::load_matrix_sync(bh, &Bh[(ks * 16) * LDB + wn * 64 + j * 16], LDB);
                wmma::load_matrix_sync(bl, &Bl[(ks * 16) * LDB + wn * 64 + j * 16], LDB);
#pragma unroll
                for (int i = 0; i < 2; i++) {
                    wmma::mma_sync(acc[i][j], ah[i], bh, acc[i][j]);
                    wmma::mma_sync(acc[i][j], ah[i], bl, acc[i][j]);
                    wmma::mma_sync(acc[i][j], al[i], bh, acc[i][j]);
                }
            }
        }
        __syncthreads();
    }

    int er = lane >> 1;
    int ec = (lane & 1) << 3;
    float* st = &stage[warp * 320];
#pragma unroll
    for (int i = 0; i < 2; i++) {
#pragma unroll
        for (int j = 0; j < 4; j++) {
            wmma::store_matrix_sync(st, acc[i][j], 20, wmma::mem_row_major);
            __syncwarp();
            int gcol = col0 + wn * 64 + j * 16 + ec;
            int grow = row0 + wm * 32 + i * 16 + er;
            float o[8];
#pragma unroll
            for (int q = 0; q < 8; q++) o[q] = st[er * 20 + ec + q];
            if (jb.bias) {
                float4 b0 = *reinterpret_cast<const float4*>(&jb.bias[gcol]);
                float4 b1 = *reinterpret_cast<const float4*>(&jb.bias[gcol + 4]);
                o[0] += b0.x; o[1] += b0.y; o[2] += b0.z; o[3] += b0.w;
                o[4] += b1.x; o[5] += b1.y; o[6] += b1.z; o[7] += b1.w;
            }
            if (jb.relu) {
#pragma unroll
                for (int q = 0; q < 8; q++) o[q] = o[q] > 0.f ? o[q] : 0.f;
            }
            if (grow < M) {
                *reinterpret_cast<float4*>(&jb.C[(size_t)grow * 256 + gcol]) =
                    *reinterpret_cast<float4*>(&o[0]);
                *reinterpret_cast<float4*>(&jb.C[(size_t)grow * 256 + gcol + 4]) =
                    *reinterpret_cast<float4*>(&o[4]);
                if (jb.bfcopy) {
                    __nv_bfloat162 c0 = __floats2bfloat162_rn(o[0], o[1]);
                    __nv_bfloat162 c1 = __floats2bfloat162_rn(o[2], o[3]);
                    __nv_bfloat162 c2 = __floats2bfloat162_rn(o[4], o[5]);
                    __nv_bfloat162 c3 = __floats2bfloat162_rn(o[6], o[7]);
                    uint4 pk = make_uint4(*reinterpret_cast<uint32_t*>(&c0),
                                          *reinterpret_cast<uint32_t*>(&c1),
                                          *reinterpret_cast<uint32_t*>(&c2),
                                          *reinterpret_cast<uint32_t*>(&c3));
                    *reinterpret_cast<uint4*>(&jb.bfcopy[(size_t)grow * 256 + gcol]) = pk;
                }
            }
            __syncwarp();
        }
    }
}

// ================= launch =================
extern "C" void kernel_launch(void* const* d_in, const int* in_sizes, int n_in,
                              void* d_out, int out_size) {
    const float* x    = (const float*)d_in[0];
    const int*   ei   = (const int*)d_in[1];
    const float* Wn   = (const float*)d_in[2];
    const float* bn   = (const float*)d_in[3];
    const float* We   = (const float*)d_in[4];
    const float* be   = (const float*)d_in[5];
    const float* Ws1  = (const float*)d_in[6];
    const float* bs1  = (const float*)d_in[7];
    const float* Ws2  = (const float*)d_in[8];
    const float* bs2  = (const float*)d_in[9];
    const float* Wh1  = (const float*)d_in[10];
    const float* bh1  = (const float*)d_in[11];
    const float* Wh2  = (const float*)d_in[12];
    const float* bh2  = (const float*)d_in[13];

    const int H = in_sizes[3];            // 256
    const int F = in_sizes[2] / H;        // 256
    const int N = in_sizes[0] / F;
    const int E = in_sizes[1] / 2;
    const int WORDS = (N + 31) / 32;
    (void)n_in; (void)out_size;

    const int* row = ei;
    const int* col = ei + E;

    float* out1 = (float*)d_out;
    float* out2 = out1 + (size_t)N * 256;
    float* out3 = out2 + (size_t)E * 256;
    float* out4 = out3 + (size_t)N * 256;

    float *pP, *pQ, *pNbr, *pF2, *pS1, *pT1;
    __nv_bfloat16* pNTb;
    cudaGetSymbolAddress((void**)&pP,  g_P);
    cudaGetSymbolAddress((void**)&pQ,  g_Q);
    cudaGetSymbolAddress((void**)&pNbr, g_nbr);
    cudaGetSymbolAddress((void**)&pF2, g_f2);
    cudaGetSymbolAddress((void**)&pS1, g_S1);
    cudaGetSymbolAddress((void**)&pT1, g_T1);
    cudaGetSymbolAddress((void**)&pNTb, g_NTb);

    cudaFuncSetAttribute(gemm_wmma, cudaFuncAttributeMaxDynamicSharedMemorySize, W8_TOTAL);
    cudaFuncSetAttribute(feat2_gemm, cudaFuncAttributeMaxDynamicSharedMemorySize, FGS_TOTAL);

    int mt = (N + 127) / 128;

    const int BO_WN  = 0;
    const int BO_WET = 65536;
    const int BO_WEB = 131072;
    const int BO_WS1 = 196608;
    const int BO_WS2 = 327680;
    const int BO_WH1 = 393216;
    const int BO_WH2 = 589824;

    // (0) fused prep: zero + grid barrier + CSR/bitset build + weight split
    {
        PrepJob p0 = {Wn, 256, BO_WN};
        PrepJob p1 = {We, 256, BO_WET};
        PrepJob p2 = {We + (size_t)256 * 256, 256, BO_WEB};
        PrepJob p3 = {Ws1, 512, BO_WS1};
        PrepJob p4 = {Ws2, 256, BO_WS2};
        PrepJob p5 = {Wh1, 768, BO_WH1};
        PrepJob p6 = {Wh2, 256, BO_WH2};
        fused_prep<<<148, 256>>>(row, col, E, p0, p1, p2, p3, p4, p5, p6, N, WORDS);
    }

    // (1) fused tokenizer GEMMs (job0 also mirrors out1 -> g_NTb in bf16)
    {
        GJob ja = {x, nullptr, nullptr, bn, out1, pNTb,    BO_WN,  1, 0};
        GJob jb = {x, nullptr, nullptr, be, pP,   nullptr, BO_WET, 1, 0};
        GJob jc = {x, nullptr, nullptr, nullptr, pQ, nullptr, BO_WEB, 1, 0};
        gemm_wmma<<<dim3(2, mt, 3), 256, W8_TOTAL>>>(ja, jb, jc, N);
    }

    // (2) hop1 (also resets the fused_prep barrier counter for the next replay)
    hop1_kernel<<<N, 256>>>(out1, N, WORDS);

    // (3) feat2  <- PROFILED SLOT (the ~360us-vs-~90us hypothesis test)
    {
        int nstages = (WORDS + 3) / 4;
        dim3 fg(2, (N + 63) / 64);
        feat2_gemm<<<fg, 256, FGS_TOTAL>>>(N, WORDS, nstages);
    }

    // (4) edge_tok
    {
        long long etot = (long long)E * 32;
        int etb = (int)((etot + 255) / 256);
        edge_tok_kernel<<<etb, 256>>>(row, col, out2, E);
    }

    // (5) MLP layer 1
    {
        GJob ja = {out1, pNbr, nullptr, bs1, pS1, nullptr, BO_WS1, 2, 1};
        GJob jb = {out1, pNbr, pF2,     bh1, pT1, nullptr, BO_WH1, 3, 1};
        gemm_wmma<<<dim3(2, mt, 2), 256, W8_TOTAL>>>(ja, jb, ja, N);
    }
    // (6) MLP layer 2
    {
        GJob ja = {pS1, nullptr, nullptr, bs2, out3, nullptr, BO_WS2, 1, 0};
        GJob jb = {pT1, nullptr, nullptr, bh2, out4, nullptr, BO_WH2, 1, 0};
        gemm_wmma<<<dim3(2, mt, 2), 256, W8_TOTAL>>>(ja, jb, ja, N);
    }
}

// round 15
// speedup vs baseline: 1.1793x; 1.1793x over previous
#include <cuda_runtime.h>
#include <cuda_bf16.h>
#include <mma.h>
#include <cstdint>

using namespace nvcuda;

// ================= static scratch (no allocs allowed) =================
#define MAXN 10240
#define MAXW 320   // ceil(MAXN/32)
#define CSR_STRIDE 96

__device__ float   g_P[MAXN * 256];
__device__ float   g_Q[MAXN * 256];
__device__ float   g_nbr[MAXN * 256];
__device__ float   g_f2[MAXN * 256];
__device__ float   g_f2b[MAXN * 256];
__device__ float   g_S1[MAXN * 256];
__device__ float   g_T1[MAXN * 256];
__device__ unsigned g_AB[MAXN * MAXW];
__device__ unsigned g_RB[MAXN * MAXW];
__device__ int     g_degcnt[MAXN];
__device__ int     g_csrp[MAXN * CSR_STRIDE];
__device__ float   g_cnt2[MAXN];
__device__ int     g_sync;     // grid barrier counter for fused_prep (reset by hop1)
// pre-split bf16 weights, [k][n] row-major per job: 655360 bf16 each
__device__ __nv_bfloat16 g_Bh[655360];
__device__ __nv_bfloat16 g_Bl[655360];
// bf16 copy of node_tokens (feat2 GEMM B-matrix); written by tokenizer GEMM epilogue
__device__ __nv_bfloat16 g_NTb[MAXN * 256];

// ================= small ptx helpers =================
__device__ __forceinline__ uint32_t smem_u32(const void* p) {
    uint32_t a;
    asm("{ .reg .u64 t; cvta.to.shared.u64 t, %1; cvt.u32.u64 %0, t; }" : "=r"(a) : "l"(p));
    return a;
}
#define CP_COMMIT() asm volatile("cp.async.commit_group;" ::: "memory")
#define CP_WAIT0()  asm volatile("cp.async.wait_group 0;" ::: "memory")

// ================= fused prep: zero + weight split + grid barrier + CSR/bitset build =================
struct PrepJob { const float* W; int K; int boff; };

__global__ __launch_bounds__(256)
void fused_prep(const int* __restrict__ row, const int* __restrict__ col, int E,
                PrepJob p0, PrepJob p1, PrepJob p2, PrepJob p3,
                PrepJob p4, PrepJob p5, PrepJob p6, int n, int words) {
    int tid = threadIdx.x;
    size_t gid = (size_t)blockIdx.x * blockDim.x + tid;
    size_t stride = (size_t)gridDim.x * blockDim.x;

    size_t ztot = (size_t)n * words;
    for (size_t i = gid; i < ztot; i += stride) {
        g_AB[i] = 0u;
        if (i < (size_t)n) g_degcnt[i] = 0;
    }

    __threadfence();
    __syncthreads();
    if (tid == 0) {
        atomicAdd(&g_sync, 1);
        while (*(volatile int*)&g_sync < (int)gridDim.x) {}
    }
    __syncthreads();

    for (size_t e = gid; e < (size_t)E; e += stride) {
        int r = row[e], c = col[e];
        int slot = atomicAdd(&g_degcnt[r], 1);
        if (slot < CSR_STRIDE) g_csrp[r * CSR_STRIDE + slot] = c;
        atomicOr(&g_AB[(size_t)r * words + (c >> 5)], 1u << (c & 31));
    }

    PrepJob jobs[7] = {p0, p1, p2, p3, p4, p5, p6};
    const int total = 655360;
    for (size_t e = gid; e < (size_t)total; e += stride) {
        int rem = (int)e, j = 0;
        while (rem >= 256 * jobs[j].K) { rem -= 256 * jobs[j].K; j++; }
        int nn = rem & 255;
        int k  = rem >> 8;
        float x = jobs[j].W[(size_t)k * 256 + nn];
        __nv_bfloat16 h = __float2bfloat16(x);
        __nv_bfloat16 l = __float2bfloat16(x - __bfloat162float(h));
        int dst = jobs[j].boff + k * 256 + nn;
        g_Bh[dst] = h;
        g_Bl[dst] = l;
    }
}

// ================= 1-hop: nbr_mean + reach bitset + cnt2 (also resets g_sync) =================
__global__ void hop1_kernel(const float* __restrict__ NT, int n, int words) {
    if (blockIdx.x == 0 && threadIdx.x == 0) g_sync = 0;
    int i = blockIdx.x;
    int t = threadIdx.x;
    int t2 = 256 + t;
    int deg = g_degcnt[i];
    int cnt = deg < CSR_STRIDE ? deg : CSR_STRIDE;
    const int* csr = &g_csrp[i * CSR_STRIDE];
    unsigned w0 = 0u, w1 = 0u;
    float acc = 0.f;
    for (int p = 0; p < cnt; p++) {
        int j = csr[p];
        const unsigned* abr = &g_AB[(size_t)j * words];
        if (t < words)  w0 |= abr[t];
        if (t2 < words) w1 |= abr[t2];
        acc += NT[(size_t)j * 256 + t];
    }
    int wi = i >> 5;
    unsigned sb = 1u << (i & 31);
    if (wi == t)  w0 &= ~sb;
    if (wi == t2) w1 &= ~sb;
    if (t < words)  g_RB[(size_t)i * words + t]  = w0;
    if (t2 < words) g_RB[(size_t)i * words + t2] = w1;

    float inv = deg > 0 ? 1.f / (float)deg : 0.f;
    g_nbr[(size_t)i * 256 + t] = acc * inv;

    __shared__ int red[256];
    red[t] = __popc(w0) + __popc(w1);
    __syncthreads();
    for (int off = 128; off > 0; off >>= 1) {
        if (t < off) red[t] += red[t + off];
        __syncthreads();
    }
    if (t == 0) g_cnt2[i] = (float)red[0];
}

// ================= edge tokens: 32B/thread, streaming stores =================
__global__ void edge_tok_kernel(const int* __restrict__ row, const int* __restrict__ col,
                                float* __restrict__ out2, int E) {
    long long idx = (long long)blockIdx.x * blockDim.x + threadIdx.x;
    long long total = (long long)E * 32;
    if (idx >= total) return;
    int e = (int)(idx >> 5);
    int u = (int)(idx & 31) << 1;
    int r = row[e], c = col[e];
    const float4* P4 = reinterpret_cast<const float4*>(g_P);
    const float4* Q4 = reinterpret_cast<const float4*>(g_Q);
    float4 a0 = P4[(size_t)r * 64 + u];
    float4 a1 = P4[(size_t)r * 64 + u + 1];
    float4 b0 = Q4[(size_t)c * 64 + u];
    float4 b1 = Q4[(size_t)c * 64 + u + 1];
    float4 o0, o1;
    o0.x = a0.x + b0.x; o0.y = a0.y + b0.y; o0.z = a0.z + b0.z; o0.w = a0.w + b0.w;
    o1.x = a1.x + b1.x; o1.y = a1.y + b1.y; o1.z = a1.z + b1.z; o1.w = a1.w + b1.w;
    float4* dst = reinterpret_cast<float4*>(out2) + ((size_t)e * 64 + u);
    __stcs(dst, o0);
    __stcs(dst + 1, o1);
}

// ================= feat2 v8: 128x128 tile, 32x64 warps, split-K 2 =================
// partial[i][:] = sum over this CTA's K-range of M2[i][k] * NTb[k][:]
// blockIdx: x = col half (0/1), y = 128-node tile, z = K half.
// Warp = 32 rows x 64 cols (2x4 acc frags): per k16 step 2A+4B loads, 8 MMAs.
#define F8_LDA 72
#define F8_LDB 136
#define F8S_A 0                       // 128*72*2  = 18432 (epilogue stage overlays)
#define F8S_B 18432                   // 64*136*2  = 17408
#define F8S_TOTAL 35840

__global__ __launch_bounds__(256, 2)
void feat2_gemm(int n, int words, int nstages) {
    extern __shared__ __align__(16) char fsm[];
    uint32_t sbase = smem_u32(fsm);
    __nv_bfloat16* Ab = (__nv_bfloat16*)(fsm + F8S_A);
    __nv_bfloat16* Bb = (__nv_bfloat16*)(fsm + F8S_B);
    float* stage = (float*)(fsm + F8S_A);   // reused after main loop

    int tid  = threadIdx.x;
    int warp = tid >> 5;
    int lane = tid & 31;
    int wm = warp >> 1;          // 0..3 : 32-row strip
    int wn = warp & 1;           // 0..1 : 64-col half
    int row0 = blockIdx.y * 128;
    int col0 = blockIdx.x * 128;
    float* out = (blockIdx.z == 0) ? g_f2 : g_f2b;

    int half = (nstages + 1) >> 1;
    int st0 = blockIdx.z * half;
    int st1 = st0 + half; if (st1 > nstages) st1 = nstages;

    wmma::fragment<wmma::accumulator, 16, 16, 16, float> acc[2][4];
#pragma unroll
    for (int i = 0; i < 2; i++)
#pragma unroll
        for (int j = 0; j < 4; j++) wmma::fill_fragment(acc[i][j], 0.f);

    int ar = tid >> 1;           // 0..127 : A row
    int ah = tid & 1;            // 16-bit group pair selector
    int anode = row0 + ar;

    for (int st = st0; st < st1; st++) {
        // ---- B: cp.async 64 k-rows x 128 cols ----
        {
            int k0 = st * 64;
#pragma unroll
            for (int u = 0; u < 4; u++) {
                int v = tid + u * 256;       // 0..1023
                int k = v >> 4;              // 0..63
                int n16 = (v & 15) << 3;     // bf16 col
                uint32_t dst = sbase + F8S_B + (k * F8_LDB + n16) * 2;
                const char* src;
                int sz;
                if (k0 + k < n) {
                    src = (const char*)&g_NTb[(size_t)(k0 + k) * 256 + col0 + n16];
                    sz = 16;
                } else {
                    src = (const char*)&g_NTb[0];
                    sz = 0;
                }
                asm volatile("cp.async.cg.shared.global [%0], [%1], 16, %2;"
                             :: "r"(dst), "l"(src), "r"(sz));
            }
            CP_COMMIT();
        }
        // ---- A: expand 128 x 64 mask bits to bf16 0/1 ----
#pragma unroll
        for (int gsel = 0; gsel < 2; gsel++) {
            int g = ah * 2 + gsel;           // 16-bit group 0..3
            unsigned wordv = 0u;
            int widx = st * 2 + (g >> 1);
            if (anode < n && widx < words) wordv = g_RB[(size_t)anode * words + widx];
            unsigned bits = (wordv >> ((g & 1) * 16)) & 0xFFFFu;
            uint32_t pk[8];
#pragma unroll
            for (int i = 0; i < 8; i++) {
                uint32_t lo = (bits >> (2 * i)) & 1u;
                uint32_t hi = (bits >> (2 * i + 1)) & 1u;
                pk[i] = (lo ? 0x3F80u : 0u) | (hi ? 0x3F800000u : 0u);
            }
            uint32_t* dst = reinterpret_cast<uint32_t*>(&Ab[ar * F8_LDA + g * 16]);
            *reinterpret_cast<uint4*>(dst)     = make_uint4(pk[0], pk[1], pk[2], pk[3]);
            *reinterpret_cast<uint4*>(dst + 4) = make_uint4(pk[4], pk[5], pk[6], pk[7]);
        }
        CP_WAIT0();
        __syncthreads();

        // ---- 4 k16 steps: 2 A frags reused over 4 B frags ----
#pragma unroll
        for (int ks = 0; ks < 4; ks++) {
            wmma::fragment<wmma::matrix_a, 16, 16, 16, __nv_bfloat16, wmma::row_major> af[2];
#pragma unroll
            for (int i = 0; i < 2; i++)
                wmma::load_matrix_sync(af[i], &Ab[(wm * 32 + i * 16) * F8_LDA + ks * 16], F8_LDA);
#pragma unroll
            for (int j = 0; j < 4; j++) {
                wmma::fragment<wmma::matrix_b, 16, 16, 16, __nv_bfloat16, wmma::row_major> bf;
                wmma::load_matrix_sync(bf, &Bb[(ks * 16) * F8_LDB + wn * 64 + j * 16], F8_LDB);
#pragma unroll
                for (int i = 0; i < 2; i++)
                    wmma::mma_sync(acc[i][j], af[i], bf, acc[i][j]);
            }
        }
        __syncthreads();
    }

    // ---- epilogue: write RAW partial sums (divide happens in f2_reduce) ----
    int er = lane >> 1;
    int ec = (lane & 1) << 3;
    float* st = &stage[warp * 320];
#pragma unroll
    for (int i = 0; i < 2; i++) {
#pragma unroll
        for (int j = 0; j < 4; j++) {
            wmma::store_matrix_sync(st, acc[i][j], 20, wmma::mem_row_major);
            __syncwarp();
            int grow = row0 + wm * 32 + i * 16 + er;
            int gcol = col0 + wn * 64 + j * 16 + ec;
            if (grow < n) {
                float o[8];
#pragma unroll
                for (int q = 0; q < 8; q++) o[q] = st[er * 20 + ec + q];
                *reinterpret_cast<float4*>(&out[(size_t)grow * 256 + gcol]) =
                    *reinterpret_cast<float4*>(&o[0]);
                *reinterpret_cast<float4*>(&out[(size_t)grow * 256 + gcol + 4]) =
                    *reinterpret_cast<float4*>(&o[4]);
            }
            __syncwarp();
        }
    }
}

// ================= f2 reduce: f2 = (f2 + f2b) / cnt2 =================
__global__ void f2_reduce(int n) {
    int idx = blockIdx.x * blockDim.x + threadIdx.x;
    int total = n * 64;
    if (idx >= total) return;
    int rowi = idx >> 6;
    float c = g_cnt2[rowi];
    float inv = c > 0.f ? 1.f / c : 0.f;
    float4 a = reinterpret_cast<const float4*>(g_f2)[idx];
    float4 b = reinterpret_cast<const float4*>(g_f2b)[idx];
    float4 o;
    o.x = (a.x + b.x) * inv; o.y = (a.y + b.y) * inv;
    o.z = (a.z + b.z) * inv; o.w = (a.w + b.w) * inv;
    reinterpret_cast<float4*>(g_f2)[idx] = o;
}

// ================= GEMM: wmma bf16 hi/lo 3-pass, 128x128 tile =================
struct GJob {
    const float* A0; const float* A1; const float* A2;
    const float* bias; float* C;
    __nv_bfloat16* bfcopy;
    int boff; int nblk; int relu;
};

#define W8_AH 0
#define W8_AL 18432
#define W8_BH 36864
#define W8_BL 54272
#define W8_ST 71680
#define W8_TOTAL 81920

#define LDA 72
#define LDB 136

__global__ __launch_bounds__(256, 2)
void gemm_wmma(GJob j0, GJob j1, GJob j2, int M) {
    extern __shared__ __align__(32) char smem[];
    __nv_bfloat16* Ah = (__nv_bfloat16*)(smem + W8_AH);
    __nv_bfloat16* Al = (__nv_bfloat16*)(smem + W8_AL);
    __nv_bfloat16* Bh = (__nv_bfloat16*)(smem + W8_BH);
    __nv_bfloat16* Bl = (__nv_bfloat16*)(smem + W8_BL);
    float* stage = (float*)(smem + W8_ST);

    GJob jb = (blockIdx.z == 0) ? j0 : ((blockIdx.z == 1) ? j1 : j2);
    int tid  = threadIdx.x;
    int warp = tid >> 5;
    int lane = tid & 31;
    int wm = warp >> 1;
    int wn = warp & 1;
    int row0 = blockIdx.y * 128;
    int col0 = blockIdx.x * 128;

    wmma::fragment<wmma::accumulator, 16, 16, 16, float> acc[2][4];
#pragma unroll
    for (int i = 0; i < 2; i++)
#pragma unroll
        for (int j = 0; j < 4; j++) wmma::fill_fragment(acc[i][j], 0.f);

    int a_r = tid >> 1;
    int a_c = (tid & 1) << 5;
    int gar = row0 + a_r;

    int nchunks = jb.nblk * 4;
    for (int ch = 0; ch < nchunks; ch++) {
        int kt = ch * 64;
        const float* Ap = (kt < 256) ? jb.A0 : ((kt < 512) ? jb.A1 : jb.A2);
        int ko = kt & 255;

#pragma unroll
        for (int u = 0; u < 8; u++) {
            int c = a_c + u * 4;
            float4 x = make_float4(0.f, 0.f, 0.f, 0.f);
            if (gar < M) x = *reinterpret_cast<const float4*>(&Ap[(size_t)gar * 256 + ko + c]);
            __nv_bfloat16 h0 = __float2bfloat16(x.x);
            __nv_bfloat16 h1 = __float2bfloat16(x.y);
            __nv_bfloat16 h2 = __float2bfloat16(x.z);
            __nv_bfloat16 h3 = __float2bfloat16(x.w);
            __nv_bfloat16 l0 = __float2bfloat16(x.x - __bfloat162float(h0));
            __nv_bfloat16 l1 = __float2bfloat16(x.y - __bfloat162float(h1));
            __nv_bfloat16 l2 = __float2bfloat16(x.z - __bfloat162float(h2));
            __nv_bfloat16 l3 = __float2bfloat16(x.w - __bfloat162float(h3));
            uint32_t hA = (uint32_t)__bfloat16_as_ushort(h0) | ((uint32_t)__bfloat16_as_ushort(h1) << 16);
            uint32_t hB = (uint32_t)__bfloat16_as_ushort(h2) | ((uint32_t)__bfloat16_as_ushort(h3) << 16);
            uint32_t lA = (uint32_t)__bfloat16_as_ushort(l0) | ((uint32_t)__bfloat16_as_ushort(l1) << 16);
            uint32_t lB = (uint32_t)__bfloat16_as_ushort(l2) | ((uint32_t)__bfloat16_as_ushort(l3) << 16);
            *reinterpret_cast<uint2*>(&Ah[a_r * LDA + c]) = make_uint2(hA, hB);
            *reinterpret_cast<uint2*>(&Al[a_r * LDA + c]) = make_uint2(lA, lB);
        }
        {
            int boff = jb.boff + kt * 256 + col0;
#pragma unroll
            for (int u = 0; u < 4; u++) {
                int v = tid + u * 256;
                int k = v >> 4;
                int n8 = (v & 15) << 3;
                *reinterpret_cast<uint4*>(&Bh[k * LDB + n8]) =
                    *reinterpret_cast<const uint4*>(&g_Bh[boff + k * 256 + n8]);
                *reinterpret_cast<uint4*>(&Bl[k * LDB + n8]) =
                    *reinterpret_cast<const uint4*>(&g_Bl[boff + k * 256 + n8]);
            }
        }
        __syncthreads();

#pragma unroll
        for (int ks = 0; ks < 4; ks++) {
            wmma::fragment<wmma::matrix_a, 16, 16, 16, __nv_bfloat16, wmma::row_major> ah[2], al[2];
#pragma unroll
            for (int i = 0; i < 2; i++) {
                wmma::load_matrix_sync(ah[i], &Ah[(wm * 32 + i * 16) * LDA + ks * 16], LDA);
                wmma::load_matrix_sync(al[i], &Al[(wm * 32 + i * 16) * LDA + ks * 16], LDA);
            }
#pragma unroll
            for (int j = 0; j < 4; j++) {
                wmma::fragment<wmma::matrix_b, 16, 16, 16, __nv_bfloat16, wmma::row_major> bh, bl;
                wmma::load_matrix_sync(bh, &Bh[(ks * 16) * LDB + wn * 64 + j * 16], LDB);
                wmma::load_matrix_sync(bl, &Bl[(ks * 16) * LDB + wn * 64 + j * 16], LDB);
#pragma unroll
                for (int i = 0; i < 2; i++) {
                    wmma::mma_sync(acc[i][j], ah[i], bh, acc[i][j]);
                    wmma::mma_sync(acc[i][j], ah[i], bl, acc[i][j]);
                    wmma::mma_sync(acc[i][j], al[i], bh, acc[i][j]);
                }
            }
        }
        __syncthreads();
    }

    int er = lane >> 1;
    int ec = (lane & 1) << 3;
    float* st = &stage[warp * 320];
#pragma unroll
    for (int i = 0; i < 2; i++) {
#pragma unroll
        for (int j = 0; j < 4; j++) {
            wmma::store_matrix_sync(st, acc[i][j], 20, wmma::mem_row_major);
            __syncwarp();
            int gcol = col0 + wn * 64 + j * 16 + ec;
            int grow = row0 + wm * 32 + i * 16 + er;
            float o[8];
#pragma unroll
            for (int q = 0; q < 8; q++) o[q] = st[er * 20 + ec + q];
            if (jb.bias) {
                float4 b0 = *reinterpret_cast<const float4*>(&jb.bias[gcol]);
                float4 b1 = *reinterpret_cast<const float4*>(&jb.bias[gcol + 4]);
                o[0] += b0.x; o[1] += b0.y; o[2] += b0.z; o[3] += b0.w;
                o[4] += b1.x; o[5] += b1.y; o[6] += b1.z; o[7] += b1.w;
            }
            if (jb.relu) {
#pragma unroll
                for (int q = 0; q < 8; q++) o[q] = o[q] > 0.f ? o[q] : 0.f;
            }
            if (grow < M) {
                *reinterpret_cast<float4*>(&jb.C[(size_t)grow * 256 + gcol]) =
                    *reinterpret_cast<float4*>(&o[0]);
                *reinterpret_cast<float4*>(&jb.C[(size_t)grow * 256 + gcol + 4]) =
                    *reinterpret_cast<float4*>(&o[4]);
                if (jb.bfcopy) {
                    __nv_bfloat162 c0 = __floats2bfloat162_rn(o[0], o[1]);
                    __nv_bfloat162 c1 = __floats2bfloat162_rn(o[2], o[3]);
                    __nv_bfloat162 c2 = __floats2bfloat162_rn(o[4], o[5]);
                    __nv_bfloat162 c3 = __floats2bfloat162_rn(o[6], o[7]);
                    uint4 pk = make_uint4(*reinterpret_cast<uint32_t*>(&c0),
                                          *reinterpret_cast<uint32_t*>(&c1),
                                          *reinterpret_cast<uint32_t*>(&c2),
                                          *reinterpret_cast<uint32_t*>(&c3));
                    *reinterpret_cast<uint4*>(&jb.bfcopy[(size_t)grow * 256 + gcol]) = pk;
                }
            }
            __syncwarp();
        }
    }
}

// ================= launch =================
extern "C" void kernel_launch(void* const* d_in, const int* in_sizes, int n_in,
                              void* d_out, int out_size) {
    const float* x    = (const float*)d_in[0];
    const int*   ei   = (const int*)d_in[1];
    const float* Wn   = (const float*)d_in[2];
    const float* bn   = (const float*)d_in[3];
    const float* We   = (const float*)d_in[4];
    const float* be   = (const float*)d_in[5];
    const float* Ws1  = (const float*)d_in[6];
    const float* bs1  = (const float*)d_in[7];
    const float* Ws2  = (const float*)d_in[8];
    const float* bs2  = (const float*)d_in[9];
    const float* Wh1  = (const float*)d_in[10];
    const float* bh1  = (const float*)d_in[11];
    const float* Wh2  = (const float*)d_in[12];
    const float* bh2  = (const float*)d_in[13];

    const int H = in_sizes[3];            // 256
    const int F = in_sizes[2] / H;        // 256
    const int N = in_sizes[0] / F;
    const int E = in_sizes[1] / 2;
    const int WORDS = (N + 31) / 32;
    (void)n_in; (void)out_size;

    const int* row = ei;
    const int* col = ei + E;

    float* out1 = (float*)d_out;
    float* out2 = out1 + (size_t)N * 256;
    float* out3 = out2 + (size_t)E * 256;
    float* out4 = out3 + (size_t)N * 256;

    float *pP, *pQ, *pNbr, *pF2, *pS1, *pT1;
    __nv_bfloat16* pNTb;
    cudaGetSymbolAddress((void**)&pP,  g_P);
    cudaGetSymbolAddress((void**)&pQ,  g_Q);
    cudaGetSymbolAddress((void**)&pNbr, g_nbr);
    cudaGetSymbolAddress((void**)&pF2, g_f2);
    cudaGetSymbolAddress((void**)&pS1, g_S1);
    cudaGetSymbolAddress((void**)&pT1, g_T1);
    cudaGetSymbolAddress((void**)&pNTb, g_NTb);

    cudaFuncSetAttribute(gemm_wmma, cudaFuncAttributeMaxDynamicSharedMemorySize, W8_TOTAL);
    cudaFuncSetAttribute(feat2_gemm, cudaFuncAttributeMaxDynamicSharedMemorySize, F8S_TOTAL);

    int mt = (N + 127) / 128;

    const int BO_WN  = 0;
    const int BO_WET = 65536;
    const int BO_WEB = 131072;
    const int BO_WS1 = 196608;
    const int BO_WS2 = 327680;
    const int BO_WH1 = 393216;
    const int BO_WH2 = 589824;

    // (0) fused prep: zero + grid barrier + CSR/bitset build + weight split
    {
        PrepJob p0 = {Wn, 256, BO_WN};
        PrepJob p1 = {We, 256, BO_WET};
        PrepJob p2 = {We + (size_t)256 * 256, 256, BO_WEB};
        PrepJob p3 = {Ws1, 512, BO_WS1};
        PrepJob p4 = {Ws2, 256, BO_WS2};
        PrepJob p5 = {Wh1, 768, BO_WH1};
        PrepJob p6 = {Wh2, 256, BO_WH2};
        fused_prep<<<148, 256>>>(row, col, E, p0, p1, p2, p3, p4, p5, p6, N, WORDS);
    }

    // (1) fused tokenizer GEMMs (job0 also mirrors out1 -> g_NTb in bf16)
    {
        GJob ja = {x, nullptr, nullptr, bn, out1, pNTb,    BO_WN,  1, 0};
        GJob jb = {x, nullptr, nullptr, be, pP,   nullptr, BO_WET, 1, 0};
        GJob jc = {x, nullptr, nullptr, nullptr, pQ, nullptr, BO_WEB, 1, 0};
        gemm_wmma<<<dim3(2, mt, 3), 256, W8_TOTAL>>>(ja, jb, jc, N);
    }

    // (2) hop1 (also resets the fused_prep barrier counter for the next replay)
    hop1_kernel<<<N, 256>>>(out1, N, WORDS);

    // (3) feat2 v8  <- PROFILED SLOT (128x128 tile, 32x64 warps, split-K 2)
    {
        int nstages = (N + 63) / 64;
        dim3 fg(2, (N + 127) / 128, 2);
        feat2_gemm<<<fg, 256, F8S_TOTAL>>>(N, WORDS, nstages);
    }

    // (4) f2 reduce: f2 = (f2 + f2b) / cnt2
    {
        int total = N * 64;
        f2_reduce<<<(total + 255) / 256, 256>>>(N);
    }

    // (5) edge_tok
    {
        long long etot = (long long)E * 32;
        int etb = (int)((etot + 255) / 256);
        edge_tok_kernel<<<etb, 256>>>(row, col, out2, E);
    }

    // (6) MLP layer 1
    {
        GJob ja = {out1, pNbr, nullptr, bs1, pS1, nullptr, BO_WS1, 2, 1};
        GJob jb = {out1, pNbr, pF2,     bh1, pT1, nullptr, BO_WH1, 3, 1};
        gemm_wmma<<<dim3(2, mt, 2), 256, W8_TOTAL>>>(ja, jb, ja, N);
    }
    // (7) MLP layer 2
    {
        GJob ja = {pS1, nullptr, nullptr, bs2, out3, nullptr, BO_WS2, 1, 0};
        GJob jb = {pT1, nullptr, nullptr, bh2, out4, nullptr, BO_WH2, 1, 0};
        gemm_wmma<<<dim3(2, mt, 2), 256, W8_TOTAL>>>(ja, jb, ja, N);
    }
}